// round 13
// baseline (speedup 1.0000x reference)
#include <cuda_runtime.h>
#include <cuda_bf16.h>
#include <cstdint>
#include <math.h>

// ---------------------------------------------------------------------------
// Problem constants
// ---------------------------------------------------------------------------
#define BATCH      4
#define SEQ        1024
#define DEMB       8192
#define NHEAD      8
#define DKV        256
#define QKVDIM     (NHEAD * DKV)          // 2048
#define TOK_TOTAL  (BATCH * SEQ)          // 4096
#define PLANE      ((long)SEQ * DEMB)

// ---------------------------------------------------------------------------
// Scratch (static device allocations — no cudaMalloc allowed)
// ---------------------------------------------------------------------------
__device__ __align__(256) float  g_V[(long)BATCH * SEQ * QKVDIM];
__device__ __align__(256) float  g_S[(long)BATCH * NHEAD * SEQ * SEQ];
__device__ __align__(256) float  g_O[(long)BATCH * SEQ * DEMB];
__device__ double g_part[2048 * 2];       // per-CTA (sum, sumsq) from O-proj
__device__ double g_mean[BATCH];
__device__ double g_rstd[BATCH];

__device__ __align__(256) __nv_bfloat16 g_Xh[(long)BATCH * SEQ * DEMB];
__device__ __align__(256) __nv_bfloat16 g_Xl[(long)BATCH * SEQ * DEMB];
__device__ __align__(256) __nv_bfloat16 g_Wqkvth[(long)3 * QKVDIM * DEMB];
__device__ __align__(256) __nv_bfloat16 g_Wqkvtl[(long)3 * QKVDIM * DEMB];
__device__ __align__(256) __nv_bfloat16 g_Woth[(long)DEMB * QKVDIM];
__device__ __align__(256) __nv_bfloat16 g_Wotl[(long)DEMB * QKVDIM];
__device__ __align__(256) __nv_bfloat16 g_Qh[(long)BATCH * SEQ * QKVDIM];
__device__ __align__(256) __nv_bfloat16 g_Ql[(long)BATCH * SEQ * QKVDIM];
__device__ __align__(256) __nv_bfloat16 g_Kh[(long)BATCH * SEQ * QKVDIM];
__device__ __align__(256) __nv_bfloat16 g_Kl[(long)BATCH * SEQ * QKVDIM];
__device__ __align__(256) __nv_bfloat16 g_Vth[(long)BATCH * NHEAD * DKV * SEQ];
__device__ __align__(256) __nv_bfloat16 g_Vtl[(long)BATCH * NHEAD * DKV * SEQ];
__device__ __align__(256) __nv_bfloat16 g_Ph[(long)BATCH * NHEAD * SEQ * SEQ];
__device__ __align__(256) __nv_bfloat16 g_Pl[(long)BATCH * NHEAD * SEQ * SEQ];
__device__ __align__(256) __nv_bfloat16 g_Zh[(long)BATCH * SEQ * QKVDIM];
__device__ __align__(256) __nv_bfloat16 g_Zl[(long)BATCH * SEQ * QKVDIM];

// ---------------------------------------------------------------------------
// PTX helpers (sm_80-compatible: cp.async, ldmatrix, mma.sync)
// ---------------------------------------------------------------------------
__device__ __forceinline__ uint32_t smem_u32(const void* p) {
    uint32_t a;
    asm("{ .reg .u64 t; cvta.to.shared.u64 t, %1; cvt.u32.u64 %0, t; }"
        : "=r"(a) : "l"(p));
    return a;
}
__device__ __forceinline__ void cpasync16(uint32_t dst, const void* src) {
    asm volatile("cp.async.cg.shared.global [%0], [%1], 16;" :: "r"(dst), "l"(src));
}
__device__ __forceinline__ void cp_commit() {
    asm volatile("cp.async.commit_group;" ::: "memory");
}
template <int N> __device__ __forceinline__ void cp_wait() {
    asm volatile("cp.async.wait_group %0;" :: "n"(N) : "memory");
}
__device__ __forceinline__ void ldsm4(uint32_t* r, uint32_t addr) {
    asm volatile("ldmatrix.sync.aligned.m8n8.x4.shared.b16 {%0,%1,%2,%3}, [%4];"
                 : "=r"(r[0]), "=r"(r[1]), "=r"(r[2]), "=r"(r[3]) : "r"(addr));
}
__device__ __forceinline__ void mma16816(float* c, const uint32_t* a, const uint32_t* b) {
    asm volatile(
        "mma.sync.aligned.m16n8k16.row.col.f32.bf16.bf16.f32 "
        "{%0,%1,%2,%3}, {%4,%5,%6,%7}, {%8,%9}, {%0,%1,%2,%3};"
        : "+f"(c[0]), "+f"(c[1]), "+f"(c[2]), "+f"(c[3])
        : "r"(a[0]), "r"(a[1]), "r"(a[2]), "r"(a[3]), "r"(b[0]), "r"(b[1]));
}
__device__ __forceinline__ __nv_bfloat162 split_hi2(float x, float y) {
    __nv_bfloat162 h;
    h.x = __float2bfloat16(x); h.y = __float2bfloat16(y);
    return h;
}
__device__ __forceinline__ __nv_bfloat162 split_lo2(float x, float y, __nv_bfloat162 h) {
    __nv_bfloat162 l;
    l.x = __float2bfloat16(x - __bfloat162float(h.x));
    l.y = __float2bfloat16(y - __bfloat162float(h.y));
    return l;
}

// ---------------------------------------------------------------------------
// Split-precision bf16 GEMM on mma.sync (round-12 base + mainloop trims).
// acc = alpha * (Ah*Bh^T + Ah*Bl^T + Al*Bh^T) (+ (Dh+Dl) residual), fp32 accum.
// Tile 128x128, K-chunk 64, 3-stage cp.async pipeline, XOR-swizzled smem.
// ONE barrier per chunk (next iteration's top barrier orders stage reuse).
// B fragments loaded as paired ldsm4 (2 nt tiles / instruction).
// mode 0: outputs Cf (fp32) and/or Ch/Cl (bf16 hi/lo).
// mode 1 (fused QKV): column segment seg=col0>>11 routes to
//         seg0 -> Ch/Cl (Q), seg1 -> C2h/C2l (K), seg2 -> Cf (V fp32); ldc=2048.
// doLN: per-CTA fp64 (sum,sumsq) of outputs -> g_part[pid_m*gridDim.x + pid_n].
// Batch z: offset = (z/inner)*so + (z%inner)*si per operand.
// ---------------------------------------------------------------------------
#define KC      64
#define TILE_B  16384                     // 128 rows x 128 bytes
#define STG_B   (4 * TILE_B)              // Ah, Al, Bh, Bl per stage
#define NSTAGE  3
#define SMEM_DYN (NSTAGE * STG_B)         // 196608

__global__ __launch_bounds__(256, 1)
void mma_gemm(const __nv_bfloat16* __restrict__ Ah, const __nv_bfloat16* __restrict__ Al,
              int lda, long sAo, long sAi,
              const __nv_bfloat16* __restrict__ Bh, const __nv_bfloat16* __restrict__ Bl,
              int ldb, long sBo, long sBi,
              float* __restrict__ Cf,
              __nv_bfloat16* __restrict__ Ch, __nv_bfloat16* __restrict__ Cl,
              __nv_bfloat16* __restrict__ C2h, __nv_bfloat16* __restrict__ C2l,
              int ldc, long sCo, long sCi,
              const __nv_bfloat16* __restrict__ Dh, const __nv_bfloat16* __restrict__ Dl,
              int K, int inner, float alpha, int mode, int doLN)
{
    extern __shared__ __align__(128) char dsm_raw[];
    const uint32_t dsm0 = smem_u32(dsm_raw);

    const int tid  = threadIdx.x;
    const int lane = tid & 31;
    const int wid  = tid >> 5;
    const int wm   = wid & 1;             // warp row (2)
    const int wn   = wid >> 1;            // warp col (4)

    const int z  = blockIdx.z;
    const int zo = z / inner, zi = z - zo * inner;
    Ah += zo * sAo + zi * sAi;  Al += zo * sAo + zi * sAi;
    Bh += zo * sBo + zi * sBi;  Bl += zo * sBo + zi * sBi;
    const long coff = zo * sCo + zi * sCi;

    // grouped rasterization: GROUP M-tiles per stripe, sweep N within stripe
    int pid_m, pid_n;
    {
        const int ntm = gridDim.y, ntn = gridDim.x;
        const int lin = blockIdx.y * ntn + blockIdx.x;
        const int G = 8;
        const int width = G * ntn;
        const int grp = lin / width;
        const int rem = lin - grp * width;
        const int m0  = grp * G;
        const int gsz = (ntm - m0 < G) ? (ntm - m0) : G;
        pid_m = m0 + rem % gsz;
        pid_n = rem / gsz;
    }
    const int row0 = pid_m * 128;
    const int col0 = pid_n * 128;

    // cp.async geometry: 1024 16B-chunks per tile; 4 per thread per tile
    int rr[4], cc[4]; uint32_t swo[4];
    #pragma unroll
    for (int j = 0; j < 4; j++) {
        int idx = tid + j * 256;
        rr[j] = idx >> 3;
        cc[j] = idx & 7;
        swo[j] = (uint32_t)(rr[j] * 128 + ((cc[j] ^ (rr[j] & 7)) << 4));
    }
    const __nv_bfloat16* tp[4] = {Ah, Al, Bh, Bl};
    const int nk = K / KC;

    auto load_stage = [&](int s, int k0) {
        const uint32_t sb = dsm0 + s * STG_B;
        #pragma unroll
        for (int t = 0; t < 4; t++) {
            const __nv_bfloat16* g = tp[t];
            const long ld = (t < 2) ? lda : ldb;
            const int  rb = (t < 2) ? row0 : col0;
            const uint32_t tb = sb + t * TILE_B;
            #pragma unroll
            for (int j = 0; j < 4; j++)
                cpasync16(tb + swo[j], g + (long)(rb + rr[j]) * ld + k0 + cc[j] * 8);
        }
        cp_commit();
    };

    // ldmatrix lane geometry
    const int l7   = lane & 7;
    const int aRow = wm * 64 + l7 + ((lane >> 3) & 1) * 8;
    const int aSel = (lane >> 4) & 1;
    // B paired-ldsm4: rows via (lane>>4), k-chunk via (lane>>3)
    const int bRow = wn * 32 + l7 + ((lane >> 4) & 1) * 8;
    const int bSel = (lane >> 3) & 1;
    const uint32_t aRowOff = (uint32_t)aRow * 128;
    const uint32_t bRowOff = (uint32_t)bRow * 128;

    float acc[4][4][4];
    #pragma unroll
    for (int mt = 0; mt < 4; mt++)
        #pragma unroll
        for (int nt = 0; nt < 4; nt++)
            #pragma unroll
            for (int q = 0; q < 4; q++) acc[mt][nt][q] = 0.f;

    load_stage(0, 0);
    load_stage(1, KC);

    for (int i = 0; i < nk; ++i) {
        const int s = i % NSTAGE;
        if (i + 1 < nk) cp_wait<1>(); else cp_wait<0>();
        __syncthreads();
        if (i + 2 < nk) load_stage((i + 2) % NSTAGE, (i + 2) * KC);

        const uint32_t sb = dsm0 + s * STG_B;
        #pragma unroll
        for (int ks = 0; ks < 4; ++ks) {
            uint32_t ah[4][4], al[4][4], bh[4][2], bl[4][2];
            const uint32_t asw = (uint32_t)(((2 * ks + aSel) ^ l7) << 4);
            const uint32_t bsw = (uint32_t)(((2 * ks + bSel) ^ l7) << 4);
            #pragma unroll
            for (int mt = 0; mt < 4; mt++) {
                uint32_t ad = sb + aRowOff + mt * 2048 + asw;
                ldsm4(ah[mt], ad);
                ldsm4(al[mt], ad + TILE_B);
            }
            #pragma unroll
            for (int p = 0; p < 2; p++) {     // each ldsm4 covers 2 nt tiles
                const uint32_t bd = sb + 2 * TILE_B + bRowOff + p * 2048 + bsw;
                uint32_t t4[4];
                ldsm4(t4, bd);                // Bh
                bh[2*p][0]   = t4[0]; bh[2*p][1]   = t4[1];
                bh[2*p+1][0] = t4[2]; bh[2*p+1][1] = t4[3];
                ldsm4(t4, bd + TILE_B);       // Bl
                bl[2*p][0]   = t4[0]; bl[2*p][1]   = t4[1];
                bl[2*p+1][0] = t4[2]; bl[2*p+1][1] = t4[3];
            }
            #pragma unroll
            for (int mt = 0; mt < 4; mt++)
                #pragma unroll
                for (int nt = 0; nt < 4; nt++) {
                    mma16816(acc[mt][nt], ah[mt], bh[nt]);
                    mma16816(acc[mt][nt], ah[mt], bl[nt]);
                    mma16816(acc[mt][nt], al[mt], bh[nt]);
                }
        }
        // no bottom barrier: next iteration's top barrier (before any stage
        // write) orders all warps' fragment reads ahead of stage reuse.
    }

    // ---- epilogue: mode-based routing
    float* cf = Cf;
    __nv_bfloat16 *ch = Ch, *cl = Cl;
    int cbase = col0;
    if (mode) {
        const int seg = col0 >> 11;
        cbase = col0 & 2047;
        if (seg == 0)      { cf = nullptr; ch = Ch;  cl = Cl;  }
        else if (seg == 1) { cf = nullptr; ch = C2h; cl = C2l; }
        else               { ch = nullptr; cl = nullptr; }
    }
    if (cf) cf += coff;
    if (ch) { ch += coff; cl += coff; }
    const __nv_bfloat16* dh = Dh ? (Dh + coff) : (const __nv_bfloat16*)0;
    const __nv_bfloat16* dl = Dh ? (Dl + coff) : (const __nv_bfloat16*)0;

    float lnS = 0.f, lnS2 = 0.f;
    const int cg = lane >> 2, tg = lane & 3;
    #pragma unroll
    for (int mt = 0; mt < 4; mt++) {
        #pragma unroll
        for (int nt = 0; nt < 4; nt++) {
            const int r = row0 + wm * 64 + mt * 16 + cg;
            const int c = cbase + wn * 32 + nt * 8 + tg * 2;
            const long o0 = (long)r * ldc + c;
            const long o1 = (long)(r + 8) * ldc + c;
            float2 v0, v1;
            v0.x = acc[mt][nt][0] * alpha; v0.y = acc[mt][nt][1] * alpha;
            v1.x = acc[mt][nt][2] * alpha; v1.y = acc[mt][nt][3] * alpha;
            if (dh) {
                __nv_bfloat162 h0 = *(const __nv_bfloat162*)(dh + o0);
                __nv_bfloat162 l0 = *(const __nv_bfloat162*)(dl + o0);
                __nv_bfloat162 h1 = *(const __nv_bfloat162*)(dh + o1);
                __nv_bfloat162 l1 = *(const __nv_bfloat162*)(dl + o1);
                v0.x += __bfloat162float(h0.x) + __bfloat162float(l0.x);
                v0.y += __bfloat162float(h0.y) + __bfloat162float(l0.y);
                v1.x += __bfloat162float(h1.x) + __bfloat162float(l1.x);
                v1.y += __bfloat162float(h1.y) + __bfloat162float(l1.y);
            }
            if (doLN) {
                lnS  += v0.x + v0.y + v1.x + v1.y;
                lnS2 += v0.x * v0.x + v0.y * v0.y + v1.x * v1.x + v1.y * v1.y;
            }
            if (cf) {
                *(float2*)(cf + o0) = v0;
                *(float2*)(cf + o1) = v1;
            }
            if (ch) {
                __nv_bfloat162 h0 = split_hi2(v0.x, v0.y);
                __nv_bfloat162 h1 = split_hi2(v1.x, v1.y);
                *(__nv_bfloat162*)(ch + o0) = h0;
                *(__nv_bfloat162*)(ch + o1) = h1;
                *(__nv_bfloat162*)(cl + o0) = split_lo2(v0.x, v0.y, h0);
                *(__nv_bfloat162*)(cl + o1) = split_lo2(v1.x, v1.y, h1);
            }
        }
    }

    if (doLN) {
        // barrier before reusing smem (mainloop fragment reads may lag)
        __syncthreads();
        double* shd = (double*)dsm_raw;
        shd[tid]       = (double)lnS;
        shd[256 + tid] = (double)lnS2;
        __syncthreads();
        for (int o = 128; o; o >>= 1) {
            if (tid < o) {
                shd[tid]       += shd[tid + o];
                shd[256 + tid] += shd[256 + tid + o];
            }
            __syncthreads();
        }
        if (tid == 0) {
            const int idx = pid_m * gridDim.x + pid_n;
            g_part[idx * 2 + 0] = shd[0];
            g_part[idx * 2 + 1] = shd[256];
        }
    }
}

// ---------------------------------------------------------------------------
// fp32 [R,C] -> bf16 hi/lo transposed [C,R]  (batched via strides)
// ---------------------------------------------------------------------------
__global__ void tsplit_kernel(const float* __restrict__ in, long sIo, long sIi, int ldin,
                              __nv_bfloat16* __restrict__ hi, __nv_bfloat16* __restrict__ lo,
                              long sOo, long sOi, int ldo, int inner)
{
    __shared__ float tile[32][33];
    const int z = blockIdx.z, zo = z / inner, zi = z - zo * inner;
    in += zo * sIo + zi * sIi;
    hi += zo * sOo + zi * sOi;
    lo += zo * sOo + zi * sOi;
    const int r0 = blockIdx.y * 32, c0 = blockIdx.x * 32;
    const int tx = threadIdx.x, ty = threadIdx.y;
    #pragma unroll
    for (int i = 0; i < 4; i++)
        tile[ty + i * 8][tx] = in[(long)(r0 + ty + i * 8) * ldin + c0 + tx];
    __syncthreads();
    const int t  = ty * 32 + tx;
    const int rp = t & 15;
    const int cb = t >> 4;
    #pragma unroll
    for (int pass = 0; pass < 2; pass++) {
        const int cl_ = cb + pass * 16;
        const float v0 = tile[2 * rp][cl_];
        const float v1 = tile[2 * rp + 1][cl_];
        __nv_bfloat162 h = split_hi2(v0, v1);
        const long o = (long)(c0 + cl_) * ldo + r0 + 2 * rp;
        *(__nv_bfloat162*)(hi + o) = h;
        *(__nv_bfloat162*)(lo + o) = split_lo2(v0, v1, h);
    }
}

// ---------------------------------------------------------------------------
// Merged Q/K/V weight transpose+split: z selects source; dest = Wqkvt + z*seg
// ---------------------------------------------------------------------------
__global__ void qkv_tsplit_kernel(const float* __restrict__ wq,
                                  const float* __restrict__ wk,
                                  const float* __restrict__ wv,
                                  __nv_bfloat16* __restrict__ hi,
                                  __nv_bfloat16* __restrict__ lo)
{
    __shared__ float tile[32][33];
    const int z = blockIdx.z;
    const float* in = (z == 0) ? wq : (z == 1) ? wk : wv;
    hi += (long)z * QKVDIM * DEMB;
    lo += (long)z * QKVDIM * DEMB;
    const int r0 = blockIdx.y * 32, c0 = blockIdx.x * 32;
    const int tx = threadIdx.x, ty = threadIdx.y;
    #pragma unroll
    for (int i = 0; i < 4; i++)
        tile[ty + i * 8][tx] = in[(long)(r0 + ty + i * 8) * QKVDIM + c0 + tx];
    __syncthreads();
    const int t  = ty * 32 + tx;
    const int rp = t & 15;
    const int cb = t >> 4;
    #pragma unroll
    for (int pass = 0; pass < 2; pass++) {
        const int cl_ = cb + pass * 16;
        const float v0 = tile[2 * rp][cl_];
        const float v1 = tile[2 * rp + 1][cl_];
        __nv_bfloat162 h = split_hi2(v0, v1);
        const long o = (long)(c0 + cl_) * DEMB + r0 + 2 * rp;
        *(__nv_bfloat162*)(hi + o) = h;
        *(__nv_bfloat162*)(lo + o) = split_lo2(v0, v1, h);
    }
}

// ---------------------------------------------------------------------------
// build X (gather + transpose + PE) writing bf16 hi/lo only
// ---------------------------------------------------------------------------
__global__ void build_x_kernel(const float* __restrict__ ref,
                               const float* __restrict__ hd,
                               __nv_bfloat16* __restrict__ Xh,
                               __nv_bfloat16* __restrict__ Xl)
{
    __shared__ float tile[32][33];
    const int b  = blockIdx.z;
    const int f0 = blockIdx.x * 32;
    const int t0 = blockIdx.y * 32;
    const int tx = threadIdx.x, ty = threadIdx.y;

#pragma unroll
    for (int i = 0; i < 4; i++) {
        int f  = f0 + ty + i * 8;
        int n_ = f >> 10;
        int s  = f & 1023;
        int hh = s >> 5;
        int ww = s & 31;
        const float* src = (ww < 16)
            ? ref + ((long)(((b * 8 + n_) * 32 + hh) * 16 + ww)) * 1024
            : hd  + ((long)(((b * 8 + n_) * 32 + hh) * 16 + (ww - 16))) * 1024;
        tile[ty + i * 8][tx] = src[t0 + tx];
    }
    __syncthreads();
#pragma unroll
    for (int i = 0; i < 4; i++) {
        int t = t0 + ty + i * 8;
        int f = f0 + tx;
        float freq = __expf((float)f * (-9.210340371976184f / 4096.0f));
        float ang  = (float)t * freq;
        float pe   = (f & 1) ? cosf(ang) : sinf(ang);
        float v    = tile[tx][ty + i * 8] + 0.001f * pe;
        long  o    = (long)b * PLANE + (long)t * DEMB + f;
        __nv_bfloat16 h = __float2bfloat16(v);
        Xh[o] = h;
        Xl[o] = __float2bfloat16(v - __bfloat162float(h));
    }
}

// ---------------------------------------------------------------------------
// Softmax over rows of S, writing bf16 hi/lo P directly.
// ---------------------------------------------------------------------------
__global__ void softmax_kernel(const float* __restrict__ S,
                               __nv_bfloat16* __restrict__ Ph,
                               __nv_bfloat16* __restrict__ Pl)
{
    __shared__ float red[8];
    const int tid  = threadIdx.x;
    const int lane = tid & 31, warp = tid >> 5;
    const float4* row = (const float4*)(S + (long)blockIdx.x * SEQ);
    float4 v = row[tid];

    float m = fmaxf(fmaxf(v.x, v.y), fmaxf(v.z, v.w));
#pragma unroll
    for (int o = 16; o; o >>= 1) m = fmaxf(m, __shfl_xor_sync(~0u, m, o));
    if (lane == 0) red[warp] = m;
    __syncthreads();
    float M = red[0];
#pragma unroll
    for (int i = 1; i < 8; i++) M = fmaxf(M, red[i]);

    v.x = __expf(v.x - M); v.y = __expf(v.y - M);
    v.z = __expf(v.z - M); v.w = __expf(v.w - M);
    float s = v.x + v.y + v.z + v.w;
#pragma unroll
    for (int o = 16; o; o >>= 1) s += __shfl_xor_sync(~0u, s, o);
    __syncthreads();
    if (lane == 0) red[warp] = s;
    __syncthreads();
    float T = 0.f;
#pragma unroll
    for (int i = 0; i < 8; i++) T += red[i];
    float inv = 1.0f / T;
    v.x *= inv; v.y *= inv; v.z *= inv; v.w *= inv;

    const long o = (long)blockIdx.x * SEQ + tid * 4;
    __nv_bfloat162 h0 = split_hi2(v.x, v.y);
    __nv_bfloat162 h1 = split_hi2(v.z, v.w);
    *(__nv_bfloat162*)(Ph + o)     = h0;
    *(__nv_bfloat162*)(Ph + o + 2) = h1;
    *(__nv_bfloat162*)(Pl + o)     = split_lo2(v.x, v.y, h0);
    *(__nv_bfloat162*)(Pl + o + 2) = split_lo2(v.z, v.w, h1);
}

// ---------------------------------------------------------------------------
// LayerNorm finalize (reads per-CTA partials from O-proj) + output transform
// ---------------------------------------------------------------------------
__global__ void finalize_stats_kernel()
{
    __shared__ double sh[256], sh2[256];
    const int b = blockIdx.x, tid = threadIdx.x;
    double s = 0.0, s2 = 0.0;
    for (int i = tid; i < 512; i += 256) {
        s  += g_part[(b * 512 + i) * 2 + 0];
        s2 += g_part[(b * 512 + i) * 2 + 1];
    }
    sh[tid] = s; sh2[tid] = s2;
    __syncthreads();
    for (int o = 128; o; o >>= 1) {
        if (tid < o) { sh[tid] += sh[tid + o]; sh2[tid] += sh2[tid + o]; }
        __syncthreads();
    }
    if (tid == 0) {
        double n    = (double)PLANE;
        double mean = sh[0] / n;
        double var  = sh2[0] / n - mean * mean;
        g_mean[b] = mean;
        g_rstd[b] = rsqrt(var + 1e-6);
    }
}

__global__ void ln_out_kernel(const float* __restrict__ O,
                              const float* __restrict__ gamma,
                              const float* __restrict__ beta,
                              float* __restrict__ out)
{
    __shared__ float tile[32][33];
    const int bz = blockIdx.z;
    const int b  = bz >> 3;
    const int nf = (bz & 7) * 1024;
    const int c0 = blockIdx.x * 32;
    const int t0 = blockIdx.y * 32;
    const int tx = threadIdx.x, ty = threadIdx.y;
    const float mean = (float)g_mean[b];
    const float rstd = (float)g_rstd[b];

#pragma unroll
    for (int i = 0; i < 4; i++) {
        int t   = t0 + ty + i * 8;
        long fi = (long)t * DEMB + nf + c0 + tx;
        float v = O[(long)b * PLANE + fi];
        tile[ty + i * 8][tx] = (v - mean) * rstd * gamma[fi] + beta[fi];
    }
    __syncthreads();
#pragma unroll
    for (int i = 0; i < 4; i++) {
        int c = c0 + ty + i * 8;
        out[((long)bz * 1024 + c) * 1024 + t0 + tx] = tile[tx][ty + i * 8];
    }
}

// ---------------------------------------------------------------------------
// Launcher
// ---------------------------------------------------------------------------
extern "C" void kernel_launch(void* const* d_in, const int* in_sizes, int n_in,
                              void* d_out, int out_size)
{
    const float* ref_img = (const float*)d_in[0];
    const float* hdmap   = (const float*)d_in[1];
    const float* w_q     = (const float*)d_in[2];
    const float* w_k     = (const float*)d_in[3];
    const float* w_v     = (const float*)d_in[4];
    const float* w_o     = (const float*)d_in[5];
    const float* gamma   = (const float*)d_in[6];
    const float* beta    = (const float*)d_in[7];
    float* out = (float*)d_out;

    float *V, *S, *O;
    __nv_bfloat16 *Xh, *Xl, *Wqkvth, *Wqkvtl, *Woth, *Wotl;
    __nv_bfloat16 *Qh, *Ql, *Kh, *Kl, *Vth, *Vtl, *Ph, *Pl, *Zh, *Zl;
    cudaGetSymbolAddress((void**)&V, g_V);
    cudaGetSymbolAddress((void**)&S, g_S);     cudaGetSymbolAddress((void**)&O, g_O);
    cudaGetSymbolAddress((void**)&Xh, g_Xh);   cudaGetSymbolAddress((void**)&Xl, g_Xl);
    cudaGetSymbolAddress((void**)&Wqkvth, g_Wqkvth);
    cudaGetSymbolAddress((void**)&Wqkvtl, g_Wqkvtl);
    cudaGetSymbolAddress((void**)&Woth, g_Woth); cudaGetSymbolAddress((void**)&Wotl, g_Wotl);
    cudaGetSymbolAddress((void**)&Qh, g_Qh);   cudaGetSymbolAddress((void**)&Ql, g_Ql);
    cudaGetSymbolAddress((void**)&Kh, g_Kh);   cudaGetSymbolAddress((void**)&Kl, g_Kl);
    cudaGetSymbolAddress((void**)&Vth, g_Vth); cudaGetSymbolAddress((void**)&Vtl, g_Vtl);
    cudaGetSymbolAddress((void**)&Ph, g_Ph);   cudaGetSymbolAddress((void**)&Pl, g_Pl);
    cudaGetSymbolAddress((void**)&Zh, g_Zh);   cudaGetSymbolAddress((void**)&Zl, g_Zl);

    cudaFuncSetAttribute(mma_gemm, cudaFuncAttributeMaxDynamicSharedMemorySize, SMEM_DYN);

    const dim3 tb32x8(32, 8);

    // 1) build X (gather + transpose + PE) with fused hi/lo split (no fp32 X)
    build_x_kernel<<<dim3(DEMB / 32, SEQ / 32, BATCH), tb32x8>>>(ref_img, hdmap, Xh, Xl);

    // 2) weight transpose + split: merged q/k/v -> Wqkvt [6144, 8192]; w_o -> Wot
    qkv_tsplit_kernel<<<dim3(QKVDIM / 32, DEMB / 32, 3), tb32x8>>>(
        w_q, w_k, w_v, Wqkvth, Wqkvtl);
    tsplit_kernel<<<dim3(DEMB / 32, QKVDIM / 32, 1), tb32x8>>>(
        w_o, 0, 0, DEMB, Woth, Wotl, 0, 0, QKVDIM, 1);

    // 3) fused QKV projection: [4096,8192] x [8192,6144]
    mma_gemm<<<dim3(3 * QKVDIM / 128, TOK_TOTAL / 128, 1), 256, SMEM_DYN>>>(
        Xh, Xl, DEMB, 0, 0,
        Wqkvth, Wqkvtl, DEMB, 0, 0,
        V, Qh, Ql, Kh, Kl, QKVDIM, 0, 0,
        nullptr, nullptr, DEMB, 1, 1.0f, 1, 0);

    // 4) transpose+split V per head -> Vt[b,h,d,t]
    tsplit_kernel<<<dim3(DKV / 32, SEQ / 32, BATCH * NHEAD), tb32x8>>>(
        V, (long)SEQ * QKVDIM, DKV, QKVDIM,
        Vth, Vtl, (long)NHEAD * DKV * SEQ, (long)DKV * SEQ, SEQ, NHEAD);

    // 5) scores S = (1/16) Q K^T per (b,h)
    const long sQKo = (long)SEQ * QKVDIM;
    const long sSo  = (long)NHEAD * SEQ * SEQ;
    mma_gemm<<<dim3(SEQ / 128, SEQ / 128, BATCH * NHEAD), 256, SMEM_DYN>>>(
        Qh, Ql, QKVDIM, sQKo, DKV,
        Kh, Kl, QKVDIM, sQKo, DKV,
        S, nullptr, nullptr, nullptr, nullptr, SEQ, sSo, (long)SEQ * SEQ,
        nullptr, nullptr, DKV, NHEAD, 0.0625f, 0, 0);

    // 6) softmax with fused P split
    softmax_kernel<<<BATCH * NHEAD * SEQ, 256>>>(S, Ph, Pl);

    // 7) Z = P @ V per (b,h), writes Zh/Zl directly
    mma_gemm<<<dim3(DKV / 128, SEQ / 128, BATCH * NHEAD), 256, SMEM_DYN>>>(
        Ph, Pl, SEQ, sSo, (long)SEQ * SEQ,
        Vth, Vtl, SEQ, (long)NHEAD * DKV * SEQ, (long)DKV * SEQ,
        nullptr, Zh, Zl, nullptr, nullptr, QKVDIM, sQKo, DKV,
        nullptr, nullptr, SEQ, NHEAD, 1.0f, 0, 0);

    // 8) O = Z @ w_o + (Xh+Xl) residual; fused LN partial stats per CTA
    mma_gemm<<<dim3(DEMB / 128, TOK_TOTAL / 128, 1), 256, SMEM_DYN>>>(
        Zh, Zl, QKVDIM, 0, 0, Woth, Wotl, QKVDIM, 0, 0,
        O, nullptr, nullptr, nullptr, nullptr, DEMB, 0, 0,
        Xh, Xl, QKVDIM, 1, 1.0f, 0, 1);

    // 9) LayerNorm finalize + normalize/transpose out
    finalize_stats_kernel<<<BATCH, 256>>>();
    ln_out_kernel<<<dim3(32, 32, BATCH * NHEAD), tb32x8>>>(O, gamma, beta, out);
}

// round 14
// speedup vs baseline: 1.0041x; 1.0041x over previous
#include <cuda_runtime.h>
#include <cuda_bf16.h>
#include <cstdint>
#include <math.h>

// ---------------------------------------------------------------------------
// Problem constants
// ---------------------------------------------------------------------------
#define BATCH      4
#define SEQ        1024
#define DEMB       8192
#define NHEAD      8
#define DKV        256
#define QKVDIM     (NHEAD * DKV)          // 2048
#define TOK_TOTAL  (BATCH * SEQ)          // 4096
#define PLANE      ((long)SEQ * DEMB)

// ---------------------------------------------------------------------------
// Scratch (static device allocations — no cudaMalloc allowed)
// ---------------------------------------------------------------------------
__device__ __align__(256) float  g_S[(long)BATCH * NHEAD * SEQ * SEQ];
__device__ __align__(256) float  g_O[(long)BATCH * SEQ * DEMB];
__device__ double g_part[2048 * 2];       // per-CTA (sum, sumsq) from O-proj
__device__ double g_mean[BATCH];
__device__ double g_rstd[BATCH];

__device__ __align__(256) __nv_bfloat16 g_Xh[(long)BATCH * SEQ * DEMB];
__device__ __align__(256) __nv_bfloat16 g_Xl[(long)BATCH * SEQ * DEMB];
__device__ __align__(256) __nv_bfloat16 g_Wqkvth[(long)3 * QKVDIM * DEMB];
__device__ __align__(256) __nv_bfloat16 g_Wqkvtl[(long)3 * QKVDIM * DEMB];
__device__ __align__(256) __nv_bfloat16 g_Woth[(long)DEMB * QKVDIM];
__device__ __align__(256) __nv_bfloat16 g_Wotl[(long)DEMB * QKVDIM];
__device__ __align__(256) __nv_bfloat16 g_Qh[(long)BATCH * SEQ * QKVDIM];
__device__ __align__(256) __nv_bfloat16 g_Ql[(long)BATCH * SEQ * QKVDIM];
__device__ __align__(256) __nv_bfloat16 g_Kh[(long)BATCH * SEQ * QKVDIM];
__device__ __align__(256) __nv_bfloat16 g_Kl[(long)BATCH * SEQ * QKVDIM];
__device__ __align__(256) __nv_bfloat16 g_Vth[(long)BATCH * NHEAD * DKV * SEQ];
__device__ __align__(256) __nv_bfloat16 g_Vtl[(long)BATCH * NHEAD * DKV * SEQ];
__device__ __align__(256) __nv_bfloat16 g_Ph[(long)BATCH * NHEAD * SEQ * SEQ];
__device__ __align__(256) __nv_bfloat16 g_Pl[(long)BATCH * NHEAD * SEQ * SEQ];
__device__ __align__(256) __nv_bfloat16 g_Zh[(long)BATCH * SEQ * QKVDIM];
__device__ __align__(256) __nv_bfloat16 g_Zl[(long)BATCH * SEQ * QKVDIM];

// ---------------------------------------------------------------------------
// PTX helpers (sm_80-compatible: cp.async, ldmatrix, mma.sync)
// ---------------------------------------------------------------------------
__device__ __forceinline__ uint32_t smem_u32(const void* p) {
    uint32_t a;
    asm("{ .reg .u64 t; cvta.to.shared.u64 t, %1; cvt.u32.u64 %0, t; }"
        : "=r"(a) : "l"(p));
    return a;
}
__device__ __forceinline__ void cpasync16(uint32_t dst, const void* src) {
    asm volatile("cp.async.cg.shared.global [%0], [%1], 16;" :: "r"(dst), "l"(src));
}
__device__ __forceinline__ void cp_commit() {
    asm volatile("cp.async.commit_group;" ::: "memory");
}
template <int N> __device__ __forceinline__ void cp_wait() {
    asm volatile("cp.async.wait_group %0;" :: "n"(N) : "memory");
}
__device__ __forceinline__ void ldsm4(uint32_t* r, uint32_t addr) {
    asm volatile("ldmatrix.sync.aligned.m8n8.x4.shared.b16 {%0,%1,%2,%3}, [%4];"
                 : "=r"(r[0]), "=r"(r[1]), "=r"(r[2]), "=r"(r[3]) : "r"(addr));
}
__device__ __forceinline__ void ldsm2(uint32_t* r, uint32_t addr) {
    asm volatile("ldmatrix.sync.aligned.m8n8.x2.shared.b16 {%0,%1}, [%2];"
                 : "=r"(r[0]), "=r"(r[1]) : "r"(addr));
}
__device__ __forceinline__ void mma16816(float* c, const uint32_t* a, const uint32_t* b) {
    asm volatile(
        "mma.sync.aligned.m16n8k16.row.col.f32.bf16.bf16.f32 "
        "{%0,%1,%2,%3}, {%4,%5,%6,%7}, {%8,%9}, {%0,%1,%2,%3};"
        : "+f"(c[0]), "+f"(c[1]), "+f"(c[2]), "+f"(c[3])
        : "r"(a[0]), "r"(a[1]), "r"(a[2]), "r"(a[3]), "r"(b[0]), "r"(b[1]));
}
__device__ __forceinline__ __nv_bfloat162 split_hi2(float x, float y) {
    __nv_bfloat162 h;
    h.x = __float2bfloat16(x); h.y = __float2bfloat16(y);
    return h;
}
__device__ __forceinline__ __nv_bfloat162 split_lo2(float x, float y, __nv_bfloat162 h) {
    __nv_bfloat162 l;
    l.x = __float2bfloat16(x - __bfloat162float(h.x));
    l.y = __float2bfloat16(y - __bfloat162float(h.y));
    return l;
}

// ---------------------------------------------------------------------------
// Split-precision bf16 GEMM on mma.sync (round-12 proven mainloop, verbatim).
// acc = alpha * (Ah*Bh^T + Ah*Bl^T + Al*Bh^T) (+ (Dh+Dl) residual), fp32 accum.
// Tile 128x128, K-chunk 64, 3-stage cp.async pipeline, XOR-swizzled smem.
// mode 0: outputs Cf (fp32) and/or Ch/Cl (bf16 hi/lo).
// mode 1 (fused QKV): column segment seg=col0>>11 routes to
//   seg0 -> Ch/Cl (Q), seg1 -> C2h/C2l (K),
//   seg2 -> TRANSPOSED bf16 split V: Vh/Vl at [b,h,d,t] via smem bounce.
// doLN: per-CTA fp64 (sum,sumsq) of outputs -> g_part[pid_m*gridDim.x + pid_n].
// Batch z: offset = (z/inner)*so + (z%inner)*si per operand.
// ---------------------------------------------------------------------------
#define KC      64
#define TILE_B  16384                     // 128 rows x 128 bytes
#define STG_B   (4 * TILE_B)              // Ah, Al, Bh, Bl per stage
#define NSTAGE  3
#define SMEM_DYN (NSTAGE * STG_B)         // 196608

__global__ __launch_bounds__(256, 1)
void mma_gemm(const __nv_bfloat16* __restrict__ Ah, const __nv_bfloat16* __restrict__ Al,
              int lda, long sAo, long sAi,
              const __nv_bfloat16* __restrict__ Bh, const __nv_bfloat16* __restrict__ Bl,
              int ldb, long sBo, long sBi,
              float* __restrict__ Cf,
              __nv_bfloat16* __restrict__ Ch, __nv_bfloat16* __restrict__ Cl,
              __nv_bfloat16* __restrict__ C2h, __nv_bfloat16* __restrict__ C2l,
              __nv_bfloat16* __restrict__ Vh, __nv_bfloat16* __restrict__ Vl,
              int ldc, long sCo, long sCi,
              const __nv_bfloat16* __restrict__ Dh, const __nv_bfloat16* __restrict__ Dl,
              int K, int inner, float alpha, int mode, int doLN)
{
    extern __shared__ __align__(128) char dsm_raw[];
    const uint32_t dsm0 = smem_u32(dsm_raw);

    const int tid  = threadIdx.x;
    const int lane = tid & 31;
    const int wid  = tid >> 5;
    const int wm   = wid & 1;             // warp row (2)
    const int wn   = wid >> 1;            // warp col (4)

    const int z  = blockIdx.z;
    const int zo = z / inner, zi = z - zo * inner;
    Ah += zo * sAo + zi * sAi;  Al += zo * sAo + zi * sAi;
    Bh += zo * sBo + zi * sBi;  Bl += zo * sBo + zi * sBi;
    const long coff = zo * sCo + zi * sCi;

    // grouped rasterization: GROUP M-tiles per stripe, sweep N within stripe
    int pid_m, pid_n;
    {
        const int ntm = gridDim.y, ntn = gridDim.x;
        const int lin = blockIdx.y * ntn + blockIdx.x;
        const int G = 8;
        const int width = G * ntn;
        const int grp = lin / width;
        const int rem = lin - grp * width;
        const int m0  = grp * G;
        const int gsz = (ntm - m0 < G) ? (ntm - m0) : G;
        pid_m = m0 + rem % gsz;
        pid_n = rem / gsz;
    }
    const int row0 = pid_m * 128;
    const int col0 = pid_n * 128;

    // cp.async geometry: 1024 16B-chunks per tile; 4 per thread per tile
    int rr[4], cc[4]; uint32_t swo[4];
    #pragma unroll
    for (int j = 0; j < 4; j++) {
        int idx = tid + j * 256;
        rr[j] = idx >> 3;
        cc[j] = idx & 7;
        swo[j] = (uint32_t)(rr[j] * 128 + ((cc[j] ^ (rr[j] & 7)) << 4));
    }
    const __nv_bfloat16* tp[4] = {Ah, Al, Bh, Bl};
    const int nk = K / KC;

    auto load_stage = [&](int s, int k0) {
        const uint32_t sb = dsm0 + s * STG_B;
        #pragma unroll
        for (int t = 0; t < 4; t++) {
            const __nv_bfloat16* g = tp[t];
            const long ld = (t < 2) ? lda : ldb;
            const int  rb = (t < 2) ? row0 : col0;
            const uint32_t tb = sb + t * TILE_B;
            #pragma unroll
            for (int j = 0; j < 4; j++)
                cpasync16(tb + swo[j], g + (long)(rb + rr[j]) * ld + k0 + cc[j] * 8);
        }
        cp_commit();
    };

    // ldmatrix lane geometry
    const int l7   = lane & 7;
    const int aRow = wm * 64 + l7 + ((lane >> 3) & 1) * 8;
    const int aSel = (lane >> 4) & 1;
    const int bRow = wn * 32 + l7;
    const int bSel = (lane >> 3) & 1;
    const uint32_t aRowOff = (uint32_t)aRow * 128;
    const uint32_t bRowOff = (uint32_t)bRow * 128;

    float acc[4][4][4];
    #pragma unroll
    for (int mt = 0; mt < 4; mt++)
        #pragma unroll
        for (int nt = 0; nt < 4; nt++)
            #pragma unroll
            for (int q = 0; q < 4; q++) acc[mt][nt][q] = 0.f;

    load_stage(0, 0);
    load_stage(1, KC);

    for (int i = 0; i < nk; ++i) {
        const int s = i % NSTAGE;
        if (i + 1 < nk) cp_wait<1>(); else cp_wait<0>();
        __syncthreads();
        if (i + 2 < nk) load_stage((i + 2) % NSTAGE, (i + 2) * KC);

        const uint32_t sb = dsm0 + s * STG_B;
        #pragma unroll
        for (int ks = 0; ks < 4; ++ks) {
            uint32_t ah[4][4], al[4][4], bh[4][2], bl[4][2];
            const uint32_t asw = (uint32_t)(((2 * ks + aSel) ^ l7) << 4);
            const uint32_t bsw = (uint32_t)(((2 * ks + bSel) ^ l7) << 4);
            #pragma unroll
            for (int mt = 0; mt < 4; mt++) {
                uint32_t ad = sb + aRowOff + mt * 2048 + asw;
                ldsm4(ah[mt], ad);
                ldsm4(al[mt], ad + TILE_B);
            }
            #pragma unroll
            for (int nt = 0; nt < 4; nt++) {
                uint32_t bd = sb + 2 * TILE_B + bRowOff + nt * 1024 + bsw;
                ldsm2(bh[nt], bd);
                ldsm2(bl[nt], bd + TILE_B);
            }
            #pragma unroll
            for (int mt = 0; mt < 4; mt++)
                #pragma unroll
                for (int nt = 0; nt < 4; nt++) {
                    mma16816(acc[mt][nt], ah[mt], bh[nt]);
                    mma16816(acc[mt][nt], ah[mt], bl[nt]);
                    mma16816(acc[mt][nt], al[mt], bh[nt]);
                }
        }
        __syncthreads();
    }

    // ---- epilogue: mode-based routing
    float* cf = Cf;
    __nv_bfloat16 *ch = Ch, *cl = Cl;
    int cbase = col0;
    int doVT = 0;
    if (mode) {
        const int seg = col0 >> 11;
        cbase = col0 & 2047;
        if (seg == 0)      { cf = nullptr; ch = Ch;  cl = Cl;  }
        else if (seg == 1) { cf = nullptr; ch = C2h; cl = C2l; }
        else               { cf = nullptr; ch = nullptr; cl = nullptr; doVT = 1; }
    }
    if (cf) cf += coff;
    if (ch) { ch += coff; cl += coff; }
    const __nv_bfloat16* dh = Dh ? (Dh + coff) : (const __nv_bfloat16*)0;
    const __nv_bfloat16* dl = Dh ? (Dl + coff) : (const __nv_bfloat16*)0;

    float* st = (float*)dsm_raw;          // V transpose bounce: 128 x 129 fp32
    float lnS = 0.f, lnS2 = 0.f;
    const int cg = lane >> 2, tg = lane & 3;
    #pragma unroll
    for (int mt = 0; mt < 4; mt++) {
        #pragma unroll
        for (int nt = 0; nt < 4; nt++) {
            const int rl = wm * 64 + mt * 16 + cg;       // local row in tile
            const int cll = wn * 32 + nt * 8 + tg * 2;   // local col in tile
            const int r = row0 + rl;
            const int c = cbase + cll;
            const long o0 = (long)r * ldc + c;
            const long o1 = (long)(r + 8) * ldc + c;
            float2 v0, v1;
            v0.x = acc[mt][nt][0] * alpha; v0.y = acc[mt][nt][1] * alpha;
            v1.x = acc[mt][nt][2] * alpha; v1.y = acc[mt][nt][3] * alpha;
            if (dh) {
                __nv_bfloat162 h0 = *(const __nv_bfloat162*)(dh + o0);
                __nv_bfloat162 l0 = *(const __nv_bfloat162*)(dl + o0);
                __nv_bfloat162 h1 = *(const __nv_bfloat162*)(dh + o1);
                __nv_bfloat162 l1 = *(const __nv_bfloat162*)(dl + o1);
                v0.x += __bfloat162float(h0.x) + __bfloat162float(l0.x);
                v0.y += __bfloat162float(h0.y) + __bfloat162float(l0.y);
                v1.x += __bfloat162float(h1.x) + __bfloat162float(l1.x);
                v1.y += __bfloat162float(h1.y) + __bfloat162float(l1.y);
            }
            if (doLN) {
                lnS  += v0.x + v0.y + v1.x + v1.y;
                lnS2 += v0.x * v0.x + v0.y * v0.y + v1.x * v1.x + v1.y * v1.y;
            }
            if (doVT) {
                st[rl * 129 + cll]           = v0.x;
                st[rl * 129 + cll + 1]       = v0.y;
                st[(rl + 8) * 129 + cll]     = v1.x;
                st[(rl + 8) * 129 + cll + 1] = v1.y;
            }
            if (cf) {
                *(float2*)(cf + o0) = v0;
                *(float2*)(cf + o1) = v1;
            }
            if (ch) {
                __nv_bfloat162 h0 = split_hi2(v0.x, v0.y);
                __nv_bfloat162 h1 = split_hi2(v1.x, v1.y);
                *(__nv_bfloat162*)(ch + o0) = h0;
                *(__nv_bfloat162*)(ch + o1) = h1;
                *(__nv_bfloat162*)(cl + o0) = split_lo2(v0.x, v0.y, h0);
                *(__nv_bfloat162*)(cl + o1) = split_lo2(v1.x, v1.y, h1);
            }
        }
    }

    if (doVT) {
        // tile spans one batch (128 | 1024) and one head (128-tile, DKV=256)
        __syncthreads();
        const int b  = row0 >> 10;
        const int h  = cbase >> 8;
        const int d0 = cbase & 255;
        const int t0 = row0 & 1023;
        const long vbase = (((long)(b * 8 + h) * 256) + d0) * 1024 + t0;
        for (int it = tid; it < 128 * 64; it += 256) {
            const int d  = it >> 6;
            const int t2 = (it & 63) * 2;
            const float v0 = st[t2 * 129 + d];
            const float v1 = st[(t2 + 1) * 129 + d];
            __nv_bfloat162 h2 = split_hi2(v0, v1);
            const long o = vbase + (long)d * 1024 + t2;
            *(__nv_bfloat162*)(Vh + o) = h2;
            *(__nv_bfloat162*)(Vl + o) = split_lo2(v0, v1, h2);
        }
    }

    if (doLN) {
        __syncthreads();
        double* shd = (double*)dsm_raw;
        shd[tid]       = (double)lnS;
        shd[256 + tid] = (double)lnS2;
        __syncthreads();
        for (int o = 128; o; o >>= 1) {
            if (tid < o) {
                shd[tid]       += shd[tid + o];
                shd[256 + tid] += shd[256 + tid + o];
            }
            __syncthreads();
        }
        if (tid == 0) {
            const int idx = pid_m * gridDim.x + pid_n;
            g_part[idx * 2 + 0] = shd[0];
            g_part[idx * 2 + 1] = shd[256];
        }
    }
}

// ---------------------------------------------------------------------------
// fp32 [R,C] -> bf16 hi/lo transposed [C,R]  (w_o only)
// ---------------------------------------------------------------------------
__global__ void tsplit_kernel(const float* __restrict__ in, int ldin,
                              __nv_bfloat16* __restrict__ hi, __nv_bfloat16* __restrict__ lo,
                              int ldo)
{
    __shared__ float tile[32][33];
    const int r0 = blockIdx.y * 32, c0 = blockIdx.x * 32;
    const int tx = threadIdx.x, ty = threadIdx.y;
    #pragma unroll
    for (int i = 0; i < 4; i++)
        tile[ty + i * 8][tx] = in[(long)(r0 + ty + i * 8) * ldin + c0 + tx];
    __syncthreads();
    const int t  = ty * 32 + tx;
    const int rp = t & 15;
    const int cb = t >> 4;
    #pragma unroll
    for (int pass = 0; pass < 2; pass++) {
        const int cl_ = cb + pass * 16;
        const float v0 = tile[2 * rp][cl_];
        const float v1 = tile[2 * rp + 1][cl_];
        __nv_bfloat162 h = split_hi2(v0, v1);
        const long o = (long)(c0 + cl_) * ldo + r0 + 2 * rp;
        *(__nv_bfloat162*)(hi + o) = h;
        *(__nv_bfloat162*)(lo + o) = split_lo2(v0, v1, h);
    }
}

// ---------------------------------------------------------------------------
// Merged Q/K/V weight transpose+split: z selects source; dest = Wqkvt + z*seg
// ---------------------------------------------------------------------------
__global__ void qkv_tsplit_kernel(const float* __restrict__ wq,
                                  const float* __restrict__ wk,
                                  const float* __restrict__ wv,
                                  __nv_bfloat16* __restrict__ hi,
                                  __nv_bfloat16* __restrict__ lo)
{
    __shared__ float tile[32][33];
    const int z = blockIdx.z;
    const float* in = (z == 0) ? wq : (z == 1) ? wk : wv;
    hi += (long)z * QKVDIM * DEMB;
    lo += (long)z * QKVDIM * DEMB;
    const int r0 = blockIdx.y * 32, c0 = blockIdx.x * 32;
    const int tx = threadIdx.x, ty = threadIdx.y;
    #pragma unroll
    for (int i = 0; i < 4; i++)
        tile[ty + i * 8][tx] = in[(long)(r0 + ty + i * 8) * QKVDIM + c0 + tx];
    __syncthreads();
    const int t  = ty * 32 + tx;
    const int rp = t & 15;
    const int cb = t >> 4;
    #pragma unroll
    for (int pass = 0; pass < 2; pass++) {
        const int cl_ = cb + pass * 16;
        const float v0 = tile[2 * rp][cl_];
        const float v1 = tile[2 * rp + 1][cl_];
        __nv_bfloat162 h = split_hi2(v0, v1);
        const long o = (long)(c0 + cl_) * DEMB + r0 + 2 * rp;
        *(__nv_bfloat162*)(hi + o) = h;
        *(__nv_bfloat162*)(lo + o) = split_lo2(v0, v1, h);
    }
}

// ---------------------------------------------------------------------------
// build X (gather + transpose + PE) writing bf16 hi/lo only
// ---------------------------------------------------------------------------
__global__ void build_x_kernel(const float* __restrict__ ref,
                               const float* __restrict__ hd,
                               __nv_bfloat16* __restrict__ Xh,
                               __nv_bfloat16* __restrict__ Xl)
{
    __shared__ float tile[32][33];
    const int b  = blockIdx.z;
    const int f0 = blockIdx.x * 32;
    const int t0 = blockIdx.y * 32;
    const int tx = threadIdx.x, ty = threadIdx.y;

#pragma unroll
    for (int i = 0; i < 4; i++) {
        int f  = f0 + ty + i * 8;
        int n_ = f >> 10;
        int s  = f & 1023;
        int hh = s >> 5;
        int ww = s & 31;
        const float* src = (ww < 16)
            ? ref + ((long)(((b * 8 + n_) * 32 + hh) * 16 + ww)) * 1024
            : hd  + ((long)(((b * 8 + n_) * 32 + hh) * 16 + (ww - 16))) * 1024;
        tile[ty + i * 8][tx] = src[t0 + tx];
    }
    __syncthreads();
#pragma unroll
    for (int i = 0; i < 4; i++) {
        int t = t0 + ty + i * 8;
        int f = f0 + tx;
        float freq = __expf((float)f * (-9.210340371976184f / 4096.0f));
        float ang  = (float)t * freq;
        float pe   = (f & 1) ? cosf(ang) : sinf(ang);
        float v    = tile[tx][ty + i * 8] + 0.001f * pe;
        long  o    = (long)b * PLANE + (long)t * DEMB + f;
        __nv_bfloat16 h = __float2bfloat16(v);
        Xh[o] = h;
        Xl[o] = __float2bfloat16(v - __bfloat162float(h));
    }
}

// ---------------------------------------------------------------------------
// Softmax over rows of S, writing bf16 hi/lo P directly.
// ---------------------------------------------------------------------------
__global__ void softmax_kernel(const float* __restrict__ S,
                               __nv_bfloat16* __restrict__ Ph,
                               __nv_bfloat16* __restrict__ Pl)
{
    __shared__ float red[8];
    const int tid  = threadIdx.x;
    const int lane = tid & 31, warp = tid >> 5;
    const float4* row = (const float4*)(S + (long)blockIdx.x * SEQ);
    float4 v = row[tid];

    float m = fmaxf(fmaxf(v.x, v.y), fmaxf(v.z, v.w));
#pragma unroll
    for (int o = 16; o; o >>= 1) m = fmaxf(m, __shfl_xor_sync(~0u, m, o));
    if (lane == 0) red[warp] = m;
    __syncthreads();
    float M = red[0];
#pragma unroll
    for (int i = 1; i < 8; i++) M = fmaxf(M, red[i]);

    v.x = __expf(v.x - M); v.y = __expf(v.y - M);
    v.z = __expf(v.z - M); v.w = __expf(v.w - M);
    float s = v.x + v.y + v.z + v.w;
#pragma unroll
    for (int o = 16; o; o >>= 1) s += __shfl_xor_sync(~0u, s, o);
    __syncthreads();
    if (lane == 0) red[warp] = s;
    __syncthreads();
    float T = 0.f;
#pragma unroll
    for (int i = 0; i < 8; i++) T += red[i];
    float inv = 1.0f / T;
    v.x *= inv; v.y *= inv; v.z *= inv; v.w *= inv;

    const long o = (long)blockIdx.x * SEQ + tid * 4;
    __nv_bfloat162 h0 = split_hi2(v.x, v.y);
    __nv_bfloat162 h1 = split_hi2(v.z, v.w);
    *(__nv_bfloat162*)(Ph + o)     = h0;
    *(__nv_bfloat162*)(Ph + o + 2) = h1;
    *(__nv_bfloat162*)(Pl + o)     = split_lo2(v.x, v.y, h0);
    *(__nv_bfloat162*)(Pl + o + 2) = split_lo2(v.z, v.w, h1);
}

// ---------------------------------------------------------------------------
// LayerNorm finalize (reads per-CTA partials from O-proj) + output transform
// ---------------------------------------------------------------------------
__global__ void finalize_stats_kernel()
{
    __shared__ double sh[256], sh2[256];
    const int b = blockIdx.x, tid = threadIdx.x;
    double s = 0.0, s2 = 0.0;
    for (int i = tid; i < 512; i += 256) {
        s  += g_part[(b * 512 + i) * 2 + 0];
        s2 += g_part[(b * 512 + i) * 2 + 1];
    }
    sh[tid] = s; sh2[tid] = s2;
    __syncthreads();
    for (int o = 128; o; o >>= 1) {
        if (tid < o) { sh[tid] += sh[tid + o]; sh2[tid] += sh2[tid + o]; }
        __syncthreads();
    }
    if (tid == 0) {
        double n    = (double)PLANE;
        double mean = sh[0] / n;
        double var  = sh2[0] / n - mean * mean;
        g_mean[b] = mean;
        g_rstd[b] = rsqrt(var + 1e-6);
    }
}

__global__ void ln_out_kernel(const float* __restrict__ O,
                              const float* __restrict__ gamma,
                              const float* __restrict__ beta,
                              float* __restrict__ out)
{
    __shared__ float tile[32][33];
    const int bz = blockIdx.z;
    const int b  = bz >> 3;
    const int nf = (bz & 7) * 1024;
    const int c0 = blockIdx.x * 32;
    const int t0 = blockIdx.y * 32;
    const int tx = threadIdx.x, ty = threadIdx.y;
    const float mean = (float)g_mean[b];
    const float rstd = (float)g_rstd[b];

#pragma unroll
    for (int i = 0; i < 4; i++) {
        int t   = t0 + ty + i * 8;
        long fi = (long)t * DEMB + nf + c0 + tx;
        float v = O[(long)b * PLANE + fi];
        tile[ty + i * 8][tx] = (v - mean) * rstd * gamma[fi] + beta[fi];
    }
    __syncthreads();
#pragma unroll
    for (int i = 0; i < 4; i++) {
        int c = c0 + ty + i * 8;
        out[((long)bz * 1024 + c) * 1024 + t0 + tx] = tile[tx][ty + i * 8];
    }
}

// ---------------------------------------------------------------------------
// Launcher
// ---------------------------------------------------------------------------
extern "C" void kernel_launch(void* const* d_in, const int* in_sizes, int n_in,
                              void* d_out, int out_size)
{
    const float* ref_img = (const float*)d_in[0];
    const float* hdmap   = (const float*)d_in[1];
    const float* w_q     = (const float*)d_in[2];
    const float* w_k     = (const float*)d_in[3];
    const float* w_v     = (const float*)d_in[4];
    const float* w_o     = (const float*)d_in[5];
    const float* gamma   = (const float*)d_in[6];
    const float* beta    = (const float*)d_in[7];
    float* out = (float*)d_out;

    float *S, *O;
    __nv_bfloat16 *Xh, *Xl, *Wqkvth, *Wqkvtl, *Woth, *Wotl;
    __nv_bfloat16 *Qh, *Ql, *Kh, *Kl, *Vth, *Vtl, *Ph, *Pl, *Zh, *Zl;
    cudaGetSymbolAddress((void**)&S, g_S);     cudaGetSymbolAddress((void**)&O, g_O);
    cudaGetSymbolAddress((void**)&Xh, g_Xh);   cudaGetSymbolAddress((void**)&Xl, g_Xl);
    cudaGetSymbolAddress((void**)&Wqkvth, g_Wqkvth);
    cudaGetSymbolAddress((void**)&Wqkvtl, g_Wqkvtl);
    cudaGetSymbolAddress((void**)&Woth, g_Woth); cudaGetSymbolAddress((void**)&Wotl, g_Wotl);
    cudaGetSymbolAddress((void**)&Qh, g_Qh);   cudaGetSymbolAddress((void**)&Ql, g_Ql);
    cudaGetSymbolAddress((void**)&Kh, g_Kh);   cudaGetSymbolAddress((void**)&Kl, g_Kl);
    cudaGetSymbolAddress((void**)&Vth, g_Vth); cudaGetSymbolAddress((void**)&Vtl, g_Vtl);
    cudaGetSymbolAddress((void**)&Ph, g_Ph);   cudaGetSymbolAddress((void**)&Pl, g_Pl);
    cudaGetSymbolAddress((void**)&Zh, g_Zh);   cudaGetSymbolAddress((void**)&Zl, g_Zl);

    cudaFuncSetAttribute(mma_gemm, cudaFuncAttributeMaxDynamicSharedMemorySize, SMEM_DYN);

    const dim3 tb32x8(32, 8);

    // 1) build X (gather + transpose + PE) with fused hi/lo split
    build_x_kernel<<<dim3(DEMB / 32, SEQ / 32, BATCH), tb32x8>>>(ref_img, hdmap, Xh, Xl);

    // 2) weight transpose + split
    qkv_tsplit_kernel<<<dim3(QKVDIM / 32, DEMB / 32, 3), tb32x8>>>(
        w_q, w_k, w_v, Wqkvth, Wqkvtl);
    tsplit_kernel<<<dim3(DEMB / 32, QKVDIM / 32, 1), tb32x8>>>(
        w_o, DEMB, Woth, Wotl, QKVDIM);

    // 3) fused QKV projection: [4096,8192] x [8192,6144]
    //    epilogue: seg0->Qh/Ql, seg1->Kh/Kl, seg2->Vth/Vtl (transposed, fused)
    mma_gemm<<<dim3(3 * QKVDIM / 128, TOK_TOTAL / 128, 1), 256, SMEM_DYN>>>(
        Xh, Xl, DEMB, 0, 0,
        Wqkvth, Wqkvtl, DEMB, 0, 0,
        nullptr, Qh, Ql, Kh, Kl, Vth, Vtl, QKVDIM, 0, 0,
        nullptr, nullptr, DEMB, 1, 1.0f, 1, 0);

    // 4) scores S = (1/16) Q K^T per (b,h)
    const long sQKo = (long)SEQ * QKVDIM;
    const long sSo  = (long)NHEAD * SEQ * SEQ;
    mma_gemm<<<dim3(SEQ / 128, SEQ / 128, BATCH * NHEAD), 256, SMEM_DYN>>>(
        Qh, Ql, QKVDIM, sQKo, DKV,
        Kh, Kl, QKVDIM, sQKo, DKV,
        S, nullptr, nullptr, nullptr, nullptr, nullptr, nullptr,
        SEQ, sSo, (long)SEQ * SEQ,
        nullptr, nullptr, DKV, NHEAD, 0.0625f, 0, 0);

    // 5) softmax with fused P split
    softmax_kernel<<<BATCH * NHEAD * SEQ, 256>>>(S, Ph, Pl);

    // 6) Z = P @ V per (b,h), writes Zh/Zl directly
    mma_gemm<<<dim3(DKV / 128, SEQ / 128, BATCH * NHEAD), 256, SMEM_DYN>>>(
        Ph, Pl, SEQ, sSo, (long)SEQ * SEQ,
        Vth, Vtl, SEQ, (long)NHEAD * DKV * SEQ, (long)DKV * SEQ,
        nullptr, Zh, Zl, nullptr, nullptr, nullptr, nullptr,
        QKVDIM, sQKo, DKV,
        nullptr, nullptr, SEQ, NHEAD, 1.0f, 0, 0);

    // 7) O = Z @ w_o + (Xh+Xl) residual; fused LN partial stats per CTA
    mma_gemm<<<dim3(DEMB / 128, TOK_TOTAL / 128, 1), 256, SMEM_DYN>>>(
        Zh, Zl, QKVDIM, 0, 0, Woth, Wotl, QKVDIM, 0, 0,
        O, nullptr, nullptr, nullptr, nullptr, nullptr, nullptr,
        DEMB, 0, 0,
        Xh, Xl, QKVDIM, 1, 1.0f, 0, 1);

    // 8) LayerNorm finalize + normalize/transpose out
    finalize_stats_kernel<<<BATCH, 256>>>();
    ln_out_kernel<<<dim3(32, 32, BATCH * NHEAD), tb32x8>>>(O, gamma, beta, out);
}

// round 15
// speedup vs baseline: 1.0059x; 1.0018x over previous
#include <cuda_runtime.h>
#include <cuda_bf16.h>
#include <cstdint>
#include <math.h>

// ---------------------------------------------------------------------------
// Problem constants
// ---------------------------------------------------------------------------
#define BATCH      4
#define SEQ        1024
#define DEMB       8192
#define NHEAD      8
#define DKV        256
#define QKVDIM     (NHEAD * DKV)          // 2048
#define TOK_TOTAL  (BATCH * SEQ)          // 4096
#define PLANE      ((long)SEQ * DEMB)

// ---------------------------------------------------------------------------
// Scratch (static device allocations — no cudaMalloc allowed)
// ---------------------------------------------------------------------------
__device__ __align__(256) float  g_S[(long)BATCH * NHEAD * SEQ * SEQ];
__device__ __align__(256) float  g_O[(long)BATCH * SEQ * DEMB];
__device__ double g_part[2048 * 2];       // per-CTA (sum, sumsq) from O-proj
__device__ double g_mean[BATCH];
__device__ double g_rstd[BATCH];

__device__ __align__(256) __nv_bfloat16 g_Xh[(long)BATCH * SEQ * DEMB];
__device__ __align__(256) __nv_bfloat16 g_Xl[(long)BATCH * SEQ * DEMB];
__device__ __align__(256) __nv_bfloat16 g_Wqkvth[(long)3 * QKVDIM * DEMB];
__device__ __align__(256) __nv_bfloat16 g_Wqkvtl[(long)3 * QKVDIM * DEMB];
__device__ __align__(256) __nv_bfloat16 g_Woth[(long)DEMB * QKVDIM];
__device__ __align__(256) __nv_bfloat16 g_Wotl[(long)DEMB * QKVDIM];
__device__ __align__(256) __nv_bfloat16 g_Qh[(long)BATCH * SEQ * QKVDIM];
__device__ __align__(256) __nv_bfloat16 g_Ql[(long)BATCH * SEQ * QKVDIM];
__device__ __align__(256) __nv_bfloat16 g_Kh[(long)BATCH * SEQ * QKVDIM];
__device__ __align__(256) __nv_bfloat16 g_Kl[(long)BATCH * SEQ * QKVDIM];
__device__ __align__(256) __nv_bfloat16 g_Vth[(long)BATCH * NHEAD * DKV * SEQ];
__device__ __align__(256) __nv_bfloat16 g_Vtl[(long)BATCH * NHEAD * DKV * SEQ];
__device__ __align__(256) __nv_bfloat16 g_Ph[(long)BATCH * NHEAD * SEQ * SEQ];
__device__ __align__(256) __nv_bfloat16 g_Pl[(long)BATCH * NHEAD * SEQ * SEQ];
__device__ __align__(256) __nv_bfloat16 g_Zh[(long)BATCH * SEQ * QKVDIM];
__device__ __align__(256) __nv_bfloat16 g_Zl[(long)BATCH * SEQ * QKVDIM];

// ---------------------------------------------------------------------------
// PTX helpers (sm_80-compatible: cp.async, ldmatrix, mma.sync)
// ---------------------------------------------------------------------------
__device__ __forceinline__ uint32_t smem_u32(const void* p) {
    uint32_t a;
    asm("{ .reg .u64 t; cvta.to.shared.u64 t, %1; cvt.u32.u64 %0, t; }"
        : "=r"(a) : "l"(p));
    return a;
}
__device__ __forceinline__ void cpasync16(uint32_t dst, const void* src) {
    asm volatile("cp.async.cg.shared.global [%0], [%1], 16;" :: "r"(dst), "l"(src));
}
__device__ __forceinline__ void cp_commit() {
    asm volatile("cp.async.commit_group;" ::: "memory");
}
template <int N> __device__ __forceinline__ void cp_wait() {
    asm volatile("cp.async.wait_group %0;" :: "n"(N) : "memory");
}
__device__ __forceinline__ void ldsm4(uint32_t* r, uint32_t addr) {
    asm volatile("ldmatrix.sync.aligned.m8n8.x4.shared.b16 {%0,%1,%2,%3}, [%4];"
                 : "=r"(r[0]), "=r"(r[1]), "=r"(r[2]), "=r"(r[3]) : "r"(addr));
}
__device__ __forceinline__ void ldsm2(uint32_t* r, uint32_t addr) {
    asm volatile("ldmatrix.sync.aligned.m8n8.x2.shared.b16 {%0,%1}, [%2];"
                 : "=r"(r[0]), "=r"(r[1]) : "r"(addr));
}
__device__ __forceinline__ void mma16816(float* c, const uint32_t* a, const uint32_t* b) {
    asm volatile(
        "mma.sync.aligned.m16n8k16.row.col.f32.bf16.bf16.f32 "
        "{%0,%1,%2,%3}, {%4,%5,%6,%7}, {%8,%9}, {%0,%1,%2,%3};"
        : "+f"(c[0]), "+f"(c[1]), "+f"(c[2]), "+f"(c[3])
        : "r"(a[0]), "r"(a[1]), "r"(a[2]), "r"(a[3]), "r"(b[0]), "r"(b[1]));
}
__device__ __forceinline__ __nv_bfloat162 split_hi2(float x, float y) {
    __nv_bfloat162 h;
    h.x = __float2bfloat16(x); h.y = __float2bfloat16(y);
    return h;
}
__device__ __forceinline__ __nv_bfloat162 split_lo2(float x, float y, __nv_bfloat162 h) {
    __nv_bfloat162 l;
    l.x = __float2bfloat16(x - __bfloat162float(h.x));
    l.y = __float2bfloat16(y - __bfloat162float(h.y));
    return l;
}

// ---------------------------------------------------------------------------
// Split-precision bf16 GEMM on mma.sync (round-12 proven mainloop, verbatim).
// acc = alpha * (Ah*Bh^T + Ah*Bl^T + Al*Bh^T) (+ (Dh+Dl) residual), fp32 accum.
// Tile 128x128, K-chunk 64, 3-stage cp.async pipeline, XOR-swizzled smem.
// mode 0: outputs Cf (fp32) and/or Ch/Cl (bf16 hi/lo).
// mode 1 (fused QKV): column segment seg=col0>>11 routes to
//   seg0 -> Ch/Cl (Q), seg1 -> C2h/C2l (K),
//   seg2 -> TRANSPOSED bf16 split V: Vh/Vl at [b,h,d,t] via smem bounce.
// doLN: per-CTA fp64 (sum,sumsq) of outputs -> g_part[pid_m*gridDim.x + pid_n].
// Batch z: offset = (z/inner)*so + (z%inner)*si per operand.
// ---------------------------------------------------------------------------
#define KC      64
#define TILE_B  16384                     // 128 rows x 128 bytes
#define STG_B   (4 * TILE_B)              // Ah, Al, Bh, Bl per stage
#define NSTAGE  3
#define SMEM_DYN (NSTAGE * STG_B)         // 196608

__global__ __launch_bounds__(256, 1)
void mma_gemm(const __nv_bfloat16* __restrict__ Ah, const __nv_bfloat16* __restrict__ Al,
              int lda, long sAo, long sAi,
              const __nv_bfloat16* __restrict__ Bh, const __nv_bfloat16* __restrict__ Bl,
              int ldb, long sBo, long sBi,
              float* __restrict__ Cf,
              __nv_bfloat16* __restrict__ Ch, __nv_bfloat16* __restrict__ Cl,
              __nv_bfloat16* __restrict__ C2h, __nv_bfloat16* __restrict__ C2l,
              __nv_bfloat16* __restrict__ Vh, __nv_bfloat16* __restrict__ Vl,
              int ldc, long sCo, long sCi,
              const __nv_bfloat16* __restrict__ Dh, const __nv_bfloat16* __restrict__ Dl,
              int K, int inner, float alpha, int mode, int doLN)
{
    extern __shared__ __align__(128) char dsm_raw[];
    const uint32_t dsm0 = smem_u32(dsm_raw);

    const int tid  = threadIdx.x;
    const int lane = tid & 31;
    const int wid  = tid >> 5;
    const int wm   = wid & 1;             // warp row (2)
    const int wn   = wid >> 1;            // warp col (4)

    const int z  = blockIdx.z;
    const int zo = z / inner, zi = z - zo * inner;
    Ah += zo * sAo + zi * sAi;  Al += zo * sAo + zi * sAi;
    Bh += zo * sBo + zi * sBi;  Bl += zo * sBo + zi * sBi;
    const long coff = zo * sCo + zi * sCi;

    // grouped rasterization: GROUP M-tiles per stripe, sweep N within stripe
    int pid_m, pid_n;
    {
        const int ntm = gridDim.y, ntn = gridDim.x;
        const int lin = blockIdx.y * ntn + blockIdx.x;
        const int G = 8;
        const int width = G * ntn;
        const int grp = lin / width;
        const int rem = lin - grp * width;
        const int m0  = grp * G;
        const int gsz = (ntm - m0 < G) ? (ntm - m0) : G;
        pid_m = m0 + rem % gsz;
        pid_n = rem / gsz;
    }
    const int row0 = pid_m * 128;
    const int col0 = pid_n * 128;

    // cp.async geometry: 1024 16B-chunks per tile; 4 per thread per tile
    int rr[4], cc[4]; uint32_t swo[4];
    #pragma unroll
    for (int j = 0; j < 4; j++) {
        int idx = tid + j * 256;
        rr[j] = idx >> 3;
        cc[j] = idx & 7;
        swo[j] = (uint32_t)(rr[j] * 128 + ((cc[j] ^ (rr[j] & 7)) << 4));
    }
    const __nv_bfloat16* tp[4] = {Ah, Al, Bh, Bl};
    const int nk = K / KC;

    auto load_stage = [&](int s, int k0) {
        const uint32_t sb = dsm0 + s * STG_B;
        #pragma unroll
        for (int t = 0; t < 4; t++) {
            const __nv_bfloat16* g = tp[t];
            const long ld = (t < 2) ? lda : ldb;
            const int  rb = (t < 2) ? row0 : col0;
            const uint32_t tb = sb + t * TILE_B;
            #pragma unroll
            for (int j = 0; j < 4; j++)
                cpasync16(tb + swo[j], g + (long)(rb + rr[j]) * ld + k0 + cc[j] * 8);
        }
        cp_commit();
    };

    // ldmatrix lane geometry
    const int l7   = lane & 7;
    const int aRow = wm * 64 + l7 + ((lane >> 3) & 1) * 8;
    const int aSel = (lane >> 4) & 1;
    const int bRow = wn * 32 + l7;
    const int bSel = (lane >> 3) & 1;
    const uint32_t aRowOff = (uint32_t)aRow * 128;
    const uint32_t bRowOff = (uint32_t)bRow * 128;

    float acc[4][4][4];
    #pragma unroll
    for (int mt = 0; mt < 4; mt++)
        #pragma unroll
        for (int nt = 0; nt < 4; nt++)
            #pragma unroll
            for (int q = 0; q < 4; q++) acc[mt][nt][q] = 0.f;

    load_stage(0, 0);
    load_stage(1, KC);

    for (int i = 0; i < nk; ++i) {
        const int s = i % NSTAGE;
        if (i + 1 < nk) cp_wait<1>(); else cp_wait<0>();
        __syncthreads();
        if (i + 2 < nk) load_stage((i + 2) % NSTAGE, (i + 2) * KC);

        const uint32_t sb = dsm0 + s * STG_B;
        #pragma unroll
        for (int ks = 0; ks < 4; ++ks) {
            uint32_t ah[4][4], al[4][4], bh[4][2], bl[4][2];
            const uint32_t asw = (uint32_t)(((2 * ks + aSel) ^ l7) << 4);
            const uint32_t bsw = (uint32_t)(((2 * ks + bSel) ^ l7) << 4);
            #pragma unroll
            for (int mt = 0; mt < 4; mt++) {
                uint32_t ad = sb + aRowOff + mt * 2048 + asw;
                ldsm4(ah[mt], ad);
                ldsm4(al[mt], ad + TILE_B);
            }
            #pragma unroll
            for (int nt = 0; nt < 4; nt++) {
                uint32_t bd = sb + 2 * TILE_B + bRowOff + nt * 1024 + bsw;
                ldsm2(bh[nt], bd);
                ldsm2(bl[nt], bd + TILE_B);
            }
            #pragma unroll
            for (int mt = 0; mt < 4; mt++)
                #pragma unroll
                for (int nt = 0; nt < 4; nt++) {
                    mma16816(acc[mt][nt], ah[mt], bh[nt]);
                    mma16816(acc[mt][nt], ah[mt], bl[nt]);
                    mma16816(acc[mt][nt], al[mt], bh[nt]);
                }
        }
        __syncthreads();
    }

    // ---- epilogue: mode-based routing
    float* cf = Cf;
    __nv_bfloat16 *ch = Ch, *cl = Cl;
    int cbase = col0;
    int doVT = 0;
    if (mode) {
        const int seg = col0 >> 11;
        cbase = col0 & 2047;
        if (seg == 0)      { cf = nullptr; ch = Ch;  cl = Cl;  }
        else if (seg == 1) { cf = nullptr; ch = C2h; cl = C2l; }
        else               { cf = nullptr; ch = nullptr; cl = nullptr; doVT = 1; }
    }
    if (cf) cf += coff;
    if (ch) { ch += coff; cl += coff; }
    const __nv_bfloat16* dh = Dh ? (Dh + coff) : (const __nv_bfloat16*)0;
    const __nv_bfloat16* dl = Dh ? (Dl + coff) : (const __nv_bfloat16*)0;

    float* st = (float*)dsm_raw;          // V transpose bounce: 128 x 129 fp32
    float lnS = 0.f, lnS2 = 0.f;
    const int cg = lane >> 2, tg = lane & 3;
    #pragma unroll
    for (int mt = 0; mt < 4; mt++) {
        #pragma unroll
        for (int nt = 0; nt < 4; nt++) {
            const int rl = wm * 64 + mt * 16 + cg;       // local row in tile
            const int cll = wn * 32 + nt * 8 + tg * 2;   // local col in tile
            const int r = row0 + rl;
            const int c = cbase + cll;
            const long o0 = (long)r * ldc + c;
            const long o1 = (long)(r + 8) * ldc + c;
            float2 v0, v1;
            v0.x = acc[mt][nt][0] * alpha; v0.y = acc[mt][nt][1] * alpha;
            v1.x = acc[mt][nt][2] * alpha; v1.y = acc[mt][nt][3] * alpha;
            if (dh) {
                __nv_bfloat162 h0 = *(const __nv_bfloat162*)(dh + o0);
                __nv_bfloat162 l0 = *(const __nv_bfloat162*)(dl + o0);
                __nv_bfloat162 h1 = *(const __nv_bfloat162*)(dh + o1);
                __nv_bfloat162 l1 = *(const __nv_bfloat162*)(dl + o1);
                v0.x += __bfloat162float(h0.x) + __bfloat162float(l0.x);
                v0.y += __bfloat162float(h0.y) + __bfloat162float(l0.y);
                v1.x += __bfloat162float(h1.x) + __bfloat162float(l1.x);
                v1.y += __bfloat162float(h1.y) + __bfloat162float(l1.y);
            }
            if (doLN) {
                lnS  += v0.x + v0.y + v1.x + v1.y;
                lnS2 += v0.x * v0.x + v0.y * v0.y + v1.x * v1.x + v1.y * v1.y;
            }
            if (doVT) {
                st[rl * 129 + cll]           = v0.x;
                st[rl * 129 + cll + 1]       = v0.y;
                st[(rl + 8) * 129 + cll]     = v1.x;
                st[(rl + 8) * 129 + cll + 1] = v1.y;
            }
            if (cf) {
                *(float2*)(cf + o0) = v0;
                *(float2*)(cf + o1) = v1;
            }
            if (ch) {
                __nv_bfloat162 h0 = split_hi2(v0.x, v0.y);
                __nv_bfloat162 h1 = split_hi2(v1.x, v1.y);
                *(__nv_bfloat162*)(ch + o0) = h0;
                *(__nv_bfloat162*)(ch + o1) = h1;
                *(__nv_bfloat162*)(cl + o0) = split_lo2(v0.x, v0.y, h0);
                *(__nv_bfloat162*)(cl + o1) = split_lo2(v1.x, v1.y, h1);
            }
        }
    }

    if (doVT) {
        // tile spans one batch (128 | 1024) and one head (128-tile, DKV=256)
        __syncthreads();
        const int b  = row0 >> 10;
        const int h  = cbase >> 8;
        const int d0 = cbase & 255;
        const int t0 = row0 & 1023;
        const long vbase = (((long)(b * 8 + h) * 256) + d0) * 1024 + t0;
        for (int it = tid; it < 128 * 64; it += 256) {
            const int d  = it >> 6;
            const int t2 = (it & 63) * 2;
            const float v0 = st[t2 * 129 + d];
            const float v1 = st[(t2 + 1) * 129 + d];
            __nv_bfloat162 h2 = split_hi2(v0, v1);
            const long o = vbase + (long)d * 1024 + t2;
            *(__nv_bfloat162*)(Vh + o) = h2;
            *(__nv_bfloat162*)(Vl + o) = split_lo2(v0, v1, h2);
        }
    }

    if (doLN) {
        __syncthreads();
        double* shd = (double*)dsm_raw;
        shd[tid]       = (double)lnS;
        shd[256 + tid] = (double)lnS2;
        __syncthreads();
        for (int o = 128; o; o >>= 1) {
            if (tid < o) {
                shd[tid]       += shd[tid + o];
                shd[256 + tid] += shd[256 + tid + o];
            }
            __syncthreads();
        }
        if (tid == 0) {
            const int idx = pid_m * gridDim.x + pid_n;
            g_part[idx * 2 + 0] = shd[0];
            g_part[idx * 2 + 1] = shd[256];
        }
    }
}

// ---------------------------------------------------------------------------
// fp32 [R,C] -> bf16 hi/lo transposed [C,R]  (w_o only)
// ---------------------------------------------------------------------------
__global__ void tsplit_kernel(const float* __restrict__ in, int ldin,
                              __nv_bfloat16* __restrict__ hi, __nv_bfloat16* __restrict__ lo,
                              int ldo)
{
    __shared__ float tile[32][33];
    const int r0 = blockIdx.y * 32, c0 = blockIdx.x * 32;
    const int tx = threadIdx.x, ty = threadIdx.y;
    #pragma unroll
    for (int i = 0; i < 4; i++)
        tile[ty + i * 8][tx] = in[(long)(r0 + ty + i * 8) * ldin + c0 + tx];
    __syncthreads();
    const int t  = ty * 32 + tx;
    const int rp = t & 15;
    const int cb = t >> 4;
    #pragma unroll
    for (int pass = 0; pass < 2; pass++) {
        const int cl_ = cb + pass * 16;
        const float v0 = tile[2 * rp][cl_];
        const float v1 = tile[2 * rp + 1][cl_];
        __nv_bfloat162 h = split_hi2(v0, v1);
        const long o = (long)(c0 + cl_) * ldo + r0 + 2 * rp;
        *(__nv_bfloat162*)(hi + o) = h;
        *(__nv_bfloat162*)(lo + o) = split_lo2(v0, v1, h);
    }
}

// ---------------------------------------------------------------------------
// Merged Q/K/V weight transpose+split: z selects source; dest = Wqkvt + z*seg
// ---------------------------------------------------------------------------
__global__ void qkv_tsplit_kernel(const float* __restrict__ wq,
                                  const float* __restrict__ wk,
                                  const float* __restrict__ wv,
                                  __nv_bfloat16* __restrict__ hi,
                                  __nv_bfloat16* __restrict__ lo)
{
    __shared__ float tile[32][33];
    const int z = blockIdx.z;
    const float* in = (z == 0) ? wq : (z == 1) ? wk : wv;
    hi += (long)z * QKVDIM * DEMB;
    lo += (long)z * QKVDIM * DEMB;
    const int r0 = blockIdx.y * 32, c0 = blockIdx.x * 32;
    const int tx = threadIdx.x, ty = threadIdx.y;
    #pragma unroll
    for (int i = 0; i < 4; i++)
        tile[ty + i * 8][tx] = in[(long)(r0 + ty + i * 8) * QKVDIM + c0 + tx];
    __syncthreads();
    const int t  = ty * 32 + tx;
    const int rp = t & 15;
    const int cb = t >> 4;
    #pragma unroll
    for (int pass = 0; pass < 2; pass++) {
        const int cl_ = cb + pass * 16;
        const float v0 = tile[2 * rp][cl_];
        const float v1 = tile[2 * rp + 1][cl_];
        __nv_bfloat162 h = split_hi2(v0, v1);
        const long o = (long)(c0 + cl_) * DEMB + r0 + 2 * rp;
        *(__nv_bfloat162*)(hi + o) = h;
        *(__nv_bfloat162*)(lo + o) = split_lo2(v0, v1, h);
    }
}

// ---------------------------------------------------------------------------
// build X (gather + transpose + PE) writing bf16 hi/lo only
// ---------------------------------------------------------------------------
__global__ void build_x_kernel(const float* __restrict__ ref,
                               const float* __restrict__ hd,
                               __nv_bfloat16* __restrict__ Xh,
                               __nv_bfloat16* __restrict__ Xl)
{
    __shared__ float tile[32][33];
    const int b  = blockIdx.z;
    const int f0 = blockIdx.x * 32;
    const int t0 = blockIdx.y * 32;
    const int tx = threadIdx.x, ty = threadIdx.y;

#pragma unroll
    for (int i = 0; i < 4; i++) {
        int f  = f0 + ty + i * 8;
        int n_ = f >> 10;
        int s  = f & 1023;
        int hh = s >> 5;
        int ww = s & 31;
        const float* src = (ww < 16)
            ? ref + ((long)(((b * 8 + n_) * 32 + hh) * 16 + ww)) * 1024
            : hd  + ((long)(((b * 8 + n_) * 32 + hh) * 16 + (ww - 16))) * 1024;
        tile[ty + i * 8][tx] = src[t0 + tx];
    }
    __syncthreads();
#pragma unroll
    for (int i = 0; i < 4; i++) {
        int t = t0 + ty + i * 8;
        int f = f0 + tx;
        float freq = __expf((float)f * (-9.210340371976184f / 4096.0f));
        float ang  = (float)t * freq;
        float pe   = (f & 1) ? cosf(ang) : sinf(ang);
        float v    = tile[tx][ty + i * 8] + 0.001f * pe;
        long  o    = (long)b * PLANE + (long)t * DEMB + f;
        __nv_bfloat16 h = __float2bfloat16(v);
        Xh[o] = h;
        Xl[o] = __float2bfloat16(v - __bfloat162float(h));
    }
}

// ---------------------------------------------------------------------------
// Softmax: one WARP per row (8 rows per 256-thread block), no smem, no
// block barriers. Each lane holds 32 values (8 x float4); warp shuffles only.
// Writes bf16 hi/lo P directly.
// ---------------------------------------------------------------------------
__global__ void softmax_kernel(const float* __restrict__ S,
                               __nv_bfloat16* __restrict__ Ph,
                               __nv_bfloat16* __restrict__ Pl)
{
    const int lane = threadIdx.x & 31;
    const int warp = threadIdx.x >> 5;
    const long row = (long)blockIdx.x * 8 + warp;
    const float4* rp = (const float4*)(S + row * SEQ);

    float4 v[8];
    #pragma unroll
    for (int j = 0; j < 8; j++) v[j] = rp[j * 32 + lane];

    float m = -3.4e38f;
    #pragma unroll
    for (int j = 0; j < 8; j++)
        m = fmaxf(m, fmaxf(fmaxf(v[j].x, v[j].y), fmaxf(v[j].z, v[j].w)));
    #pragma unroll
    for (int o = 16; o; o >>= 1) m = fmaxf(m, __shfl_xor_sync(~0u, m, o));

    float s = 0.f;
    #pragma unroll
    for (int j = 0; j < 8; j++) {
        v[j].x = __expf(v[j].x - m); v[j].y = __expf(v[j].y - m);
        v[j].z = __expf(v[j].z - m); v[j].w = __expf(v[j].w - m);
        s += v[j].x + v[j].y + v[j].z + v[j].w;
    }
    #pragma unroll
    for (int o = 16; o; o >>= 1) s += __shfl_xor_sync(~0u, s, o);
    const float inv = 1.0f / s;

    #pragma unroll
    for (int j = 0; j < 8; j++) {
        v[j].x *= inv; v[j].y *= inv; v[j].z *= inv; v[j].w *= inv;
        const long o = row * SEQ + (long)(j * 32 + lane) * 4;
        __nv_bfloat162 h0 = split_hi2(v[j].x, v[j].y);
        __nv_bfloat162 h1 = split_hi2(v[j].z, v[j].w);
        *(__nv_bfloat162*)(Ph + o)     = h0;
        *(__nv_bfloat162*)(Ph + o + 2) = h1;
        *(__nv_bfloat162*)(Pl + o)     = split_lo2(v[j].x, v[j].y, h0);
        *(__nv_bfloat162*)(Pl + o + 2) = split_lo2(v[j].z, v[j].w, h1);
    }
}

// ---------------------------------------------------------------------------
// LayerNorm finalize (reads per-CTA partials from O-proj) + output transform
// ---------------------------------------------------------------------------
__global__ void finalize_stats_kernel()
{
    __shared__ double sh[256], sh2[256];
    const int b = blockIdx.x, tid = threadIdx.x;
    double s = 0.0, s2 = 0.0;
    for (int i = tid; i < 512; i += 256) {
        s  += g_part[(b * 512 + i) * 2 + 0];
        s2 += g_part[(b * 512 + i) * 2 + 1];
    }
    sh[tid] = s; sh2[tid] = s2;
    __syncthreads();
    for (int o = 128; o; o >>= 1) {
        if (tid < o) { sh[tid] += sh[tid + o]; sh2[tid] += sh2[tid + o]; }
        __syncthreads();
    }
    if (tid == 0) {
        double n    = (double)PLANE;
        double mean = sh[0] / n;
        double var  = sh2[0] / n - mean * mean;
        g_mean[b] = mean;
        g_rstd[b] = rsqrt(var + 1e-6);
    }
}

__global__ void ln_out_kernel(const float* __restrict__ O,
                              const float* __restrict__ gamma,
                              const float* __restrict__ beta,
                              float* __restrict__ out)
{
    __shared__ float tile[32][33];
    const int bz = blockIdx.z;
    const int b  = bz >> 3;
    const int nf = (bz & 7) * 1024;
    const int c0 = blockIdx.x * 32;
    const int t0 = blockIdx.y * 32;
    const int tx = threadIdx.x, ty = threadIdx.y;
    const float mean = (float)g_mean[b];
    const float rstd = (float)g_rstd[b];

#pragma unroll
    for (int i = 0; i < 4; i++) {
        int t   = t0 + ty + i * 8;
        long fi = (long)t * DEMB + nf + c0 + tx;
        float v = O[(long)b * PLANE + fi];
        tile[ty + i * 8][tx] = (v - mean) * rstd * gamma[fi] + beta[fi];
    }
    __syncthreads();
#pragma unroll
    for (int i = 0; i < 4; i++) {
        int c = c0 + ty + i * 8;
        out[((long)bz * 1024 + c) * 1024 + t0 + tx] = tile[tx][ty + i * 8];
    }
}

// ---------------------------------------------------------------------------
// Launcher
// ---------------------------------------------------------------------------
extern "C" void kernel_launch(void* const* d_in, const int* in_sizes, int n_in,
                              void* d_out, int out_size)
{
    const float* ref_img = (const float*)d_in[0];
    const float* hdmap   = (const float*)d_in[1];
    const float* w_q     = (const float*)d_in[2];
    const float* w_k     = (const float*)d_in[3];
    const float* w_v     = (const float*)d_in[4];
    const float* w_o     = (const float*)d_in[5];
    const float* gamma   = (const float*)d_in[6];
    const float* beta    = (const float*)d_in[7];
    float* out = (float*)d_out;

    float *S, *O;
    __nv_bfloat16 *Xh, *Xl, *Wqkvth, *Wqkvtl, *Woth, *Wotl;
    __nv_bfloat16 *Qh, *Ql, *Kh, *Kl, *Vth, *Vtl, *Ph, *Pl, *Zh, *Zl;
    cudaGetSymbolAddress((void**)&S, g_S);     cudaGetSymbolAddress((void**)&O, g_O);
    cudaGetSymbolAddress((void**)&Xh, g_Xh);   cudaGetSymbolAddress((void**)&Xl, g_Xl);
    cudaGetSymbolAddress((void**)&Wqkvth, g_Wqkvth);
    cudaGetSymbolAddress((void**)&Wqkvtl, g_Wqkvtl);
    cudaGetSymbolAddress((void**)&Woth, g_Woth); cudaGetSymbolAddress((void**)&Wotl, g_Wotl);
    cudaGetSymbolAddress((void**)&Qh, g_Qh);   cudaGetSymbolAddress((void**)&Ql, g_Ql);
    cudaGetSymbolAddress((void**)&Kh, g_Kh);   cudaGetSymbolAddress((void**)&Kl, g_Kl);
    cudaGetSymbolAddress((void**)&Vth, g_Vth); cudaGetSymbolAddress((void**)&Vtl, g_Vtl);
    cudaGetSymbolAddress((void**)&Ph, g_Ph);   cudaGetSymbolAddress((void**)&Pl, g_Pl);
    cudaGetSymbolAddress((void**)&Zh, g_Zh);   cudaGetSymbolAddress((void**)&Zl, g_Zl);

    cudaFuncSetAttribute(mma_gemm, cudaFuncAttributeMaxDynamicSharedMemorySize, SMEM_DYN);

    const dim3 tb32x8(32, 8);

    // 1) build X (gather + transpose + PE) with fused hi/lo split
    build_x_kernel<<<dim3(DEMB / 32, SEQ / 32, BATCH), tb32x8>>>(ref_img, hdmap, Xh, Xl);

    // 2) weight transpose + split
    qkv_tsplit_kernel<<<dim3(QKVDIM / 32, DEMB / 32, 3), tb32x8>>>(
        w_q, w_k, w_v, Wqkvth, Wqkvtl);
    tsplit_kernel<<<dim3(DEMB / 32, QKVDIM / 32, 1), tb32x8>>>(
        w_o, DEMB, Woth, Wotl, QKVDIM);

    // 3) fused QKV projection: [4096,8192] x [8192,6144]
    //    epilogue: seg0->Qh/Ql, seg1->Kh/Kl, seg2->Vth/Vtl (transposed, fused)
    mma_gemm<<<dim3(3 * QKVDIM / 128, TOK_TOTAL / 128, 1), 256, SMEM_DYN>>>(
        Xh, Xl, DEMB, 0, 0,
        Wqkvth, Wqkvtl, DEMB, 0, 0,
        nullptr, Qh, Ql, Kh, Kl, Vth, Vtl, QKVDIM, 0, 0,
        nullptr, nullptr, DEMB, 1, 1.0f, 1, 0);

    // 4) scores S = (1/16) Q K^T per (b,h)
    const long sQKo = (long)SEQ * QKVDIM;
    const long sSo  = (long)NHEAD * SEQ * SEQ;
    mma_gemm<<<dim3(SEQ / 128, SEQ / 128, BATCH * NHEAD), 256, SMEM_DYN>>>(
        Qh, Ql, QKVDIM, sQKo, DKV,
        Kh, Kl, QKVDIM, sQKo, DKV,
        S, nullptr, nullptr, nullptr, nullptr, nullptr, nullptr,
        SEQ, sSo, (long)SEQ * SEQ,
        nullptr, nullptr, DKV, NHEAD, 0.0625f, 0, 0);

    // 5) softmax (warp-per-row) with fused P split
    softmax_kernel<<<BATCH * NHEAD * SEQ / 8, 256>>>(S, Ph, Pl);

    // 6) Z = P @ V per (b,h), writes Zh/Zl directly
    mma_gemm<<<dim3(DKV / 128, SEQ / 128, BATCH * NHEAD), 256, SMEM_DYN>>>(
        Ph, Pl, SEQ, sSo, (long)SEQ * SEQ,
        Vth, Vtl, SEQ, (long)NHEAD * DKV * SEQ, (long)DKV * SEQ,
        nullptr, Zh, Zl, nullptr, nullptr, nullptr, nullptr,
        QKVDIM, sQKo, DKV,
        nullptr, nullptr, SEQ, NHEAD, 1.0f, 0, 0);

    // 7) O = Z @ w_o + (Xh+Xl) residual; fused LN partial stats per CTA
    mma_gemm<<<dim3(DEMB / 128, TOK_TOTAL / 128, 1), 256, SMEM_DYN>>>(
        Zh, Zl, QKVDIM, 0, 0, Woth, Wotl, QKVDIM, 0, 0,
        O, nullptr, nullptr, nullptr, nullptr, nullptr, nullptr,
        DEMB, 0, 0,
        Xh, Xl, QKVDIM, 1, 1.0f, 0, 1);

    // 8) LayerNorm finalize + normalize/transpose out
    finalize_stats_kernel<<<BATCH, 256>>>();
    ln_out_kernel<<<dim3(32, 32, BATCH * NHEAD), tb32x8>>>(O, gamma, beta, out);
}